// round 16
// baseline (speedup 1.0000x reference)
#include <cuda_runtime.h>
#include <cuda_bf16.h>
#include <cuda_fp16.h>
#include <mma.h>
#include <stdint.h>

using namespace nvcuda;

// ---------------------------------------------------------------------------
// 2-layer GCN on GB300 — CSR-gather + tensor-core GEMMs + dual-stream overlap
// + pipelined tail (gather1/gemm2 split in halves and overlapped).
// s0: setup -> gemm1 ----------(join)-> g1a -> g1b -------> m2b -> gather2
// s2:      \-> deg->scan1->scan3->fill -/        \-> m2a -/
// ---------------------------------------------------------------------------

#define MAXN 100000
#define MAXE 2000000
#define DIN 128
#define DH  128
#define DOUT 64
#define SCAN_BLK 1024
#define NSCAN ((MAXN + SCAN_BLK - 1) / SCAN_BLK)   // 98
#define NHALF 50048                                 // 391 * 128

__device__ float  g_dinv[MAXN];
__device__ int    g_deg[MAXN];
__device__ int    g_fill[MAXN];
__device__ int    g_row_ptr[MAXN + 1];
__device__ int    g_partials[128];
__device__ int    g_col[MAXE];
__device__ __half g_h1[(size_t)MAXN * DH];
__device__ __half g_acc1[(size_t)MAXN * DH];
__device__ __half g_h2[(size_t)MAXN * DOUT];
__device__ __half g_w1h[DIN * DH];
__device__ __half g_w2h[DH * DOUT], g_w2l[DH * DOUT];
__device__ int    g_idx_is64;

__device__ __forceinline__ long long load_idx(const void* ei, long long pos, int is64) {
    if (is64) return ((const long long*)ei)[pos];
    return (long long)((const int*)ei)[pos];
}

// ---------------------------------------------------------------------------
__global__ void setup_kernel(const float* __restrict__ W1, const float* __restrict__ W2,
                             const unsigned int* __restrict__ w, long long nwords, int n) {
    int i = blockIdx.x * blockDim.x + threadIdx.x;
    if (i < DIN * DH) g_w1h[i] = __float2half_rn(W1[i]);
    if (i < DH * DOUT) {
        float wv = W2[i];
        __half h = __float2half_rn(wv);
        g_w2h[i] = h;
        g_w2l[i] = __float2half_rn(wv - __half2float(h));
    }
    if (i < n) { g_deg[i] = 0; g_fill[i] = 0; }
    if (blockIdx.x == 0) {
        __shared__ int any;
        if (threadIdx.x == 0) any = 0;
        __syncthreads();
        long long limit = nwords < 8192 ? nwords : 8192;
        for (long long j = 1 + 2 * (long long)threadIdx.x; j < limit; j += 512)
            if (w[j] != 0u) any = 1;
        __syncthreads();
        if (threadIdx.x == 0) g_idx_is64 = any ? 0 : 1;
    }
}

__global__ void deg_count_kernel(const void* __restrict__ ei, long long E) {
    const int is64 = g_idx_is64;
    long long i = (long long)blockIdx.x * blockDim.x + threadIdx.x;
    long long stride = (long long)gridDim.x * blockDim.x;
    for (; i < E; i += stride) {
        long long d = load_idx(ei, E + i, is64);
        if (d >= 0 && d < MAXN) atomicAdd(&g_deg[(int)d], 1);
    }
}

// --- 2-level exclusive scan of g_deg -> g_row_ptr, fused dinv ---------------
__global__ __launch_bounds__(256) void scan1_kernel(int n) {
    __shared__ int wsum[8], woff[8];
    const int t = threadIdx.x, lane = t & 31, wid = t >> 5;
    const int base = blockIdx.x * SCAN_BLK;
    const int i0 = base + t * 4;
    int v[4];
#pragma unroll
    for (int k = 0; k < 4; k++) v[k] = (i0 + k < n) ? g_deg[i0 + k] : 0;
#pragma unroll
    for (int k = 0; k < 4; k++)
        if (i0 + k < n) g_dinv[i0 + k] = rsqrtf((float)(v[k] + 1));
    int tsum = v[0] + v[1] + v[2] + v[3];
    int s = tsum;
#pragma unroll
    for (int off = 1; off < 32; off <<= 1) {
        int u = __shfl_up_sync(0xFFFFFFFFu, s, off);
        if (lane >= off) s += u;
    }
    if (lane == 31) wsum[wid] = s;
    __syncthreads();
    if (t == 0) {
        int run = 0;
#pragma unroll
        for (int w = 0; w < 8; w++) { woff[w] = run; run += wsum[w]; }
        g_partials[blockIdx.x] = run;
    }
    __syncthreads();
    int excl = woff[wid] + (s - tsum);
    int run = excl;
#pragma unroll
    for (int k = 0; k < 4; k++) {
        if (i0 + k < n) g_row_ptr[i0 + k] = run;
        run += v[k];
    }
}

__global__ __launch_bounds__(256) void scan3_kernel(int n, int E, int nblk) {
    __shared__ int soff[128];
    const int t = threadIdx.x;
    if (t < 32) {
        int v[4];
#pragma unroll
        for (int k = 0; k < 4; k++) {
            int idx = t * 4 + k;
            v[k] = (idx < nblk) ? g_partials[idx] : 0;
        }
        int tsum = v[0] + v[1] + v[2] + v[3];
        int s = tsum;
#pragma unroll
        for (int off = 1; off < 32; off <<= 1) {
            int u = __shfl_up_sync(0xFFFFFFFFu, s, off);
            if (t >= off) s += u;
        }
        int run = s - tsum;
#pragma unroll
        for (int k = 0; k < 4; k++) {
            soff[t * 4 + k] = run;
            run += v[k];
        }
    }
    __syncthreads();
    int i = blockIdx.x * blockDim.x + t;
    if (i < n) g_row_ptr[i] += soff[i / SCAN_BLK];
    if (i == n) g_row_ptr[n] = E;
}

__global__ void fill_kernel(const void* __restrict__ ei, long long E) {
    const int is64 = g_idx_is64;
    long long i = (long long)blockIdx.x * blockDim.x + threadIdx.x;
    long long stride = (long long)gridDim.x * blockDim.x;
    for (; i < E; i += stride) {
        long long s = load_idx(ei, i, is64);
        long long d = load_idx(ei, E + i, is64);
        if (s < 0 || s >= MAXN || d < 0 || d >= MAXN) continue;
        int pos = g_row_ptr[(int)d] + atomicAdd(&g_fill[(int)d], 1);
        g_col[pos] = (int)s;
    }
}

// ---------------------------------------------------------------------------
// GEMM1: h1 = fp16( fp16(x) @ fp16(W1) ), unscaled.
// ---------------------------------------------------------------------------
#define G1_LDX 40
#define G1_LDW 136
#define G1_SMEM 55296

__global__ __launch_bounds__(256, 2) void gemm1_mma_kernel(
    const float* __restrict__ x, int n)
{
    extern __shared__ char smem[];
    __half* sX[2] = { (__half*)smem, (__half*)(smem + 10240) };
    __half* sWh = (__half*)(smem + 20480);

    const int tid = threadIdx.x;
    const int wid = tid >> 5, lane = tid & 31;
    const int wm = wid >> 1, wn = wid & 1;
    const int row0 = blockIdx.x * 128;
    const int srow = tid >> 1, hc = tid & 1;
    const int grow_st = row0 + srow;
    const bool rowok = grow_st < n;

    for (int i = tid; i < 2048; i += 256) {
        int r = i >> 4, c = i & 15;
        *(uint4*)&sWh[r * G1_LDW + c * 8] = ((const uint4*)(g_w1h + (size_t)r * DH))[c];
    }

    wmma::fragment<wmma::accumulator, 16, 16, 16, float> acc[2][4];
#pragma unroll
    for (int mi = 0; mi < 2; mi++)
#pragma unroll
        for (int ni = 0; ni < 4; ni++) wmma::fill_fragment(acc[mi][ni], 0.f);

    float4 tmp[4];
    if (rowok) {
#pragma unroll
        for (int j = 0; j < 4; j++)
            tmp[j] = *(const float4*)&x[(size_t)grow_st * DIN + hc * 16 + j * 4];
    } else {
#pragma unroll
        for (int j = 0; j < 4; j++) tmp[j] = make_float4(0.f, 0.f, 0.f, 0.f);
    }

    for (int k0 = 0; k0 < 4; k0++) {
        const int b = k0 & 1;
        {
            __half hh[16];
            const float* tf = (const float*)tmp;
#pragma unroll
            for (int j = 0; j < 16; j++) hh[j] = __float2half_rn(tf[j]);
            *(uint4*)&sX[b][srow * G1_LDX + hc * 16]     = *(uint4*)&hh[0];
            *(uint4*)&sX[b][srow * G1_LDX + hc * 16 + 8] = *(uint4*)&hh[8];
        }
        if (k0 < 3 && rowok) {
#pragma unroll
            for (int j = 0; j < 4; j++)
                tmp[j] = *(const float4*)&x[(size_t)grow_st * DIN + (k0 + 1) * 32 + hc * 16 + j * 4];
        }
        __syncthreads();
#pragma unroll
        for (int kk = 0; kk < 32; kk += 16) {
            const int kr = k0 * 32 + kk;
            wmma::fragment<wmma::matrix_a, 16, 16, 16, __half, wmma::row_major> ah[2];
#pragma unroll
            for (int mi = 0; mi < 2; mi++)
                wmma::load_matrix_sync(ah[mi], sX[b] + (wm * 32 + mi * 16) * G1_LDX + kk, G1_LDX);
#pragma unroll
            for (int ni = 0; ni < 4; ni++) {
                wmma::fragment<wmma::matrix_b, 16, 16, 16, __half, wmma::row_major> bh;
                wmma::load_matrix_sync(bh, sWh + kr * G1_LDW + wn * 64 + ni * 16, G1_LDW);
#pragma unroll
                for (int mi = 0; mi < 2; mi++)
                    wmma::mma_sync(acc[mi][ni], ah[mi], bh, acc[mi][ni]);
            }
        }
    }

    __syncthreads();
    float* scratch = (float*)smem + wid * (32 * 36);
#pragma unroll
    for (int h = 0; h < 2; h++) {
        if (h) __syncwarp();
        wmma::store_matrix_sync(scratch,            acc[0][2*h],   36, wmma::mem_row_major);
        wmma::store_matrix_sync(scratch + 16,       acc[0][2*h+1], 36, wmma::mem_row_major);
        wmma::store_matrix_sync(scratch + 16*36,    acc[1][2*h],   36, wmma::mem_row_major);
        wmma::store_matrix_sync(scratch + 16*36+16, acc[1][2*h+1], 36, wmma::mem_row_major);
        __syncwarp();
        int grow = row0 + wm * 32 + lane;
        if (grow < n) {
            const float* sr = scratch + lane * 36;
            __half2 hh[16];
#pragma unroll
            for (int j = 0; j < 16; j++)
                hh[j] = __floats2half2_rn(sr[2*j], sr[2*j+1]);
            uint4* dst = (uint4*)&g_h1[(size_t)grow * DH + wn * 64 + h * 32];
#pragma unroll
            for (int q = 0; q < 4; q++) dst[q] = ((uint4*)hh)[q];
        }
    }
}

// ---------------------------------------------------------------------------
// gather1 over node range [v0, v1): acc1[v] = fp16(dinv[v]*h1[v] + sum ...).
// ---------------------------------------------------------------------------
__global__ __launch_bounds__(256) void gather1_kernel(int v0, int v1)
{
    const int lane = threadIdx.x & 31;
    const int v = v0 + (int)((blockIdx.x * blockDim.x + threadIdx.x) >> 5);
    if (v >= v1) return;

    const int start = g_row_ptr[v], end = g_row_ptr[v + 1];
    const float dvv = g_dinv[v];
    float4 acc;
    {
        uint2 u = *(const uint2*)&g_h1[(size_t)v * DH + lane * 4];
        float2 f0 = __half22float2(*(__half2*)&u.x);
        float2 f1 = __half22float2(*(__half2*)&u.y);
        acc = make_float4(dvv * f0.x, dvv * f0.y, dvv * f1.x, dvv * f1.y);
    }

    for (int b = start; b < end; b += 32) {
        const int cnt = min(32, end - b);
        int idx = (lane < cnt) ? g_col[b + lane] : 0;
        float dvl = (lane < cnt) ? g_dinv[idx] : 0.f;
        int j = 0;
        for (; j + 4 <= cnt; j += 4) {
            int s0 = __shfl_sync(0xFFFFFFFFu, idx, j);
            int s1 = __shfl_sync(0xFFFFFFFFu, idx, j + 1);
            int s2 = __shfl_sync(0xFFFFFFFFu, idx, j + 2);
            int s3 = __shfl_sync(0xFFFFFFFFu, idx, j + 3);
            float d0 = __shfl_sync(0xFFFFFFFFu, dvl, j);
            float d1 = __shfl_sync(0xFFFFFFFFu, dvl, j + 1);
            float d2 = __shfl_sync(0xFFFFFFFFu, dvl, j + 2);
            float d3 = __shfl_sync(0xFFFFFFFFu, dvl, j + 3);
            uint2 u0 = *(const uint2*)&g_h1[(size_t)s0 * DH + lane * 4];
            uint2 u1 = *(const uint2*)&g_h1[(size_t)s1 * DH + lane * 4];
            uint2 u2 = *(const uint2*)&g_h1[(size_t)s2 * DH + lane * 4];
            uint2 u3 = *(const uint2*)&g_h1[(size_t)s3 * DH + lane * 4];
#pragma unroll
            for (int q = 0; q < 4; q++) {
                uint2 u = (q == 0) ? u0 : (q == 1) ? u1 : (q == 2) ? u2 : u3;
                float d = (q == 0) ? d0 : (q == 1) ? d1 : (q == 2) ? d2 : d3;
                float2 f0 = __half22float2(*(__half2*)&u.x);
                float2 f1 = __half22float2(*(__half2*)&u.y);
                acc.x = fmaf(d, f0.x, acc.x); acc.y = fmaf(d, f0.y, acc.y);
                acc.z = fmaf(d, f1.x, acc.z); acc.w = fmaf(d, f1.y, acc.w);
            }
        }
        for (; j < cnt; j++) {
            int s = __shfl_sync(0xFFFFFFFFu, idx, j);
            float d = __shfl_sync(0xFFFFFFFFu, dvl, j);
            uint2 u = *(const uint2*)&g_h1[(size_t)s * DH + lane * 4];
            float2 f0 = __half22float2(*(__half2*)&u.x);
            float2 f1 = __half22float2(*(__half2*)&u.y);
            acc.x = fmaf(d, f0.x, acc.x); acc.y = fmaf(d, f0.y, acc.y);
            acc.z = fmaf(d, f1.x, acc.z); acc.w = fmaf(d, f1.y, acc.w);
        }
    }
    uint2 o;
    *(__half2*)&o.x = __floats2half2_rn(acc.x, acc.y);
    *(__half2*)&o.y = __floats2half2_rn(acc.z, acc.w);
    *(uint2*)&g_acc1[(size_t)v * DH + lane * 4] = o;
}

// ---------------------------------------------------------------------------
// GEMM2 over rows [row_base, min(row_base+128*gridDim, nmax)).
// ---------------------------------------------------------------------------
#define G2_LDX 40
#define G2_LDW 72
#define G2_SMEM 57856

__global__ __launch_bounds__(256, 2) void gemm2_mma_kernel(
    const float* __restrict__ b1, int row_base, int nmax)
{
    extern __shared__ char smem[];
    __half* sX[2] = { (__half*)smem, (__half*)(smem + 10240) };
    __half* sWh = (__half*)(smem + 20480);
    __half* sWl = (__half*)(smem + 38912);
    float*  sb1 = (float*)(smem + 57344);

    const int tid = threadIdx.x;
    const int wid = tid >> 5, lane = tid & 31;
    const int wm = wid >> 1, wn = wid & 1;
    const int row0 = row_base + blockIdx.x * 128;
    const int srow = tid >> 1, hc = tid & 1;
    const int grow_st = row0 + srow;
    const bool rowok = grow_st < nmax;
    const float dv_st = rowok ? g_dinv[grow_st] : 0.f;

    if (tid < 32) ((float4*)sb1)[tid] = ((const float4*)b1)[tid];
    for (int i = tid; i < 1024; i += 256) {
        int r = i >> 3, c = i & 7;
        *(uint4*)&sWh[r * G2_LDW + c * 8] = ((const uint4*)(g_w2h + (size_t)r * DOUT))[c];
        *(uint4*)&sWl[r * G2_LDW + c * 8] = ((const uint4*)(g_w2l + (size_t)r * DOUT))[c];
    }

    wmma::fragment<wmma::accumulator, 16, 16, 16, float> acc[2][2];
#pragma unroll
    for (int mi = 0; mi < 2; mi++)
#pragma unroll
        for (int ni = 0; ni < 2; ni++) wmma::fill_fragment(acc[mi][ni], 0.f);

    uint4 tmp16[2];
    if (rowok) {
#pragma unroll
        for (int j = 0; j < 2; j++)
            tmp16[j] = *(const uint4*)&g_acc1[(size_t)grow_st * DH + hc * 16 + j * 8];
    } else {
        tmp16[0] = tmp16[1] = make_uint4(0u, 0u, 0u, 0u);
    }

    __syncthreads();

    for (int k0 = 0; k0 < 4; k0++) {
        const int b = k0 & 1;
        {
            __half hh[16];
            const __half2* th = (const __half2*)tmp16;
#pragma unroll
            for (int j = 0; j < 8; j++) {
                float2 f = __half22float2(th[j]);
                hh[2*j]   = __float2half_rn(fmaxf(fmaf(dv_st, f.x, sb1[k0 * 32 + hc * 16 + 2*j]),   0.f));
                hh[2*j+1] = __float2half_rn(fmaxf(fmaf(dv_st, f.y, sb1[k0 * 32 + hc * 16 + 2*j+1]), 0.f));
            }
            *(uint4*)&sX[b][srow * G2_LDX + hc * 16]     = *(uint4*)&hh[0];
            *(uint4*)&sX[b][srow * G2_LDX + hc * 16 + 8] = *(uint4*)&hh[8];
        }
        if (k0 < 3 && rowok) {
#pragma unroll
            for (int j = 0; j < 2; j++)
                tmp16[j] = *(const uint4*)&g_acc1[(size_t)grow_st * DH + (k0 + 1) * 32 + hc * 16 + j * 8];
        }
        __syncthreads();
#pragma unroll
        for (int kk = 0; kk < 32; kk += 16) {
            const int kr = k0 * 32 + kk;
            wmma::fragment<wmma::matrix_a, 16, 16, 16, __half, wmma::row_major> ah[2];
#pragma unroll
            for (int mi = 0; mi < 2; mi++)
                wmma::load_matrix_sync(ah[mi], sX[b] + (wm * 32 + mi * 16) * G2_LDX + kk, G2_LDX);
#pragma unroll
            for (int ni = 0; ni < 2; ni++) {
                wmma::fragment<wmma::matrix_b, 16, 16, 16, __half, wmma::row_major> bh, bl;
                wmma::load_matrix_sync(bh, sWh + kr * G2_LDW + wn * 32 + ni * 16, G2_LDW);
                wmma::load_matrix_sync(bl, sWl + kr * G2_LDW + wn * 32 + ni * 16, G2_LDW);
#pragma unroll
                for (int mi = 0; mi < 2; mi++) {
                    wmma::mma_sync(acc[mi][ni], ah[mi], bh, acc[mi][ni]);
                    wmma::mma_sync(acc[mi][ni], ah[mi], bl, acc[mi][ni]);
                }
            }
        }
    }

    __syncthreads();
    float* scratch = (float*)(smem + 20480) + wid * (32 * 36);
    wmma::store_matrix_sync(scratch,            acc[0][0], 36, wmma::mem_row_major);
    wmma::store_matrix_sync(scratch + 16,       acc[0][1], 36, wmma::mem_row_major);
    wmma::store_matrix_sync(scratch + 16*36,    acc[1][0], 36, wmma::mem_row_major);
    wmma::store_matrix_sync(scratch + 16*36+16, acc[1][1], 36, wmma::mem_row_major);
    __syncwarp();
    int grow = row0 + wm * 32 + lane;
    if (grow < nmax) {
        float dv = g_dinv[grow];
        const float* sr = scratch + lane * 36;
        __half2 hh[16];
#pragma unroll
        for (int j = 0; j < 16; j++)
            hh[j] = __floats2half2_rn(sr[2*j] * dv, sr[2*j+1] * dv);
        uint4* dst = (uint4*)&g_h2[(size_t)grow * DOUT + wn * 32];
#pragma unroll
        for (int q = 0; q < 4; q++) dst[q] = ((uint4*)hh)[q];
    }
}

// ---------------------------------------------------------------------------
// gather2: out[v] = dinv[v]*(h2[v] + sum h2[s]) + b2.
// ---------------------------------------------------------------------------
__global__ __launch_bounds__(256) void gather2_kernel(
    float* __restrict__ out, const float* __restrict__ b2, int n)
{
    const int lane = threadIdx.x & 31;
    const int v = (blockIdx.x * blockDim.x + threadIdx.x) >> 5;
    if (v >= n) return;

    const int start = g_row_ptr[v], end = g_row_ptr[v + 1];
    float2 acc = __half22float2(*(const __half2*)&g_h2[(size_t)v * DOUT + lane * 2]);

    for (int b = start; b < end; b += 32) {
        const int cnt = min(32, end - b);
        int idx = (lane < cnt) ? g_col[b + lane] : 0;
        int j = 0;
        for (; j + 4 <= cnt; j += 4) {
            int s0 = __shfl_sync(0xFFFFFFFFu, idx, j);
            int s1 = __shfl_sync(0xFFFFFFFFu, idx, j + 1);
            int s2 = __shfl_sync(0xFFFFFFFFu, idx, j + 2);
            int s3 = __shfl_sync(0xFFFFFFFFu, idx, j + 3);
            float2 a0 = __half22float2(*(const __half2*)&g_h2[(size_t)s0 * DOUT + lane * 2]);
            float2 a1 = __half22float2(*(const __half2*)&g_h2[(size_t)s1 * DOUT + lane * 2]);
            float2 a2 = __half22float2(*(const __half2*)&g_h2[(size_t)s2 * DOUT + lane * 2]);
            float2 a3 = __half22float2(*(const __half2*)&g_h2[(size_t)s3 * DOUT + lane * 2]);
            acc.x += a0.x + a1.x + a2.x + a3.x;
            acc.y += a0.y + a1.y + a2.y + a3.y;
        }
        for (; j < cnt; j++) {
            int s = __shfl_sync(0xFFFFFFFFu, idx, j);
            float2 a = __half22float2(*(const __half2*)&g_h2[(size_t)s * DOUT + lane * 2]);
            acc.x += a.x; acc.y += a.y;
        }
    }
    float dv = g_dinv[v];
    float2 bb = *(const float2*)&b2[lane * 2];
    *(float2*)&out[(size_t)v * DOUT + lane * 2] =
        make_float2(fmaf(acc.x, dv, bb.x), fmaf(acc.y, dv, bb.y));
}

// ---------------------------------------------------------------------------
extern "C" void kernel_launch(void* const* d_in, const int* in_sizes, int n_in,
                              void* d_out, int out_size)
{
    const float* x = nullptr; const float* W1 = nullptr; const float* b1 = nullptr;
    const float* W2 = nullptr; const float* b2 = nullptr; const void* ei = nullptr;
    long long ei_elems = 0;
    for (int i = 0; i < n_in; i++) {
        switch (in_sizes[i]) {
            case MAXN * DIN: x  = (const float*)d_in[i]; break;
            case DIN * DH:   W1 = (const float*)d_in[i]; break;
            case DH:         b1 = (const float*)d_in[i]; break;
            case DH * DOUT:  W2 = (const float*)d_in[i]; break;
            case DOUT:       b2 = (const float*)d_in[i]; break;
            default:         ei = d_in[i]; ei_elems = in_sizes[i]; break;
        }
    }
    float* out = (float*)d_out;
    const int n = MAXN;
    const long long E = ei_elems / 2;
    const int nblk = (n + 127) / 128;      // 782
    const int nblkA = NHALF / 128;         // 391 (rows [0, NHALF))
    const int nblkB = nblk - nblkA;        // 391 (rows [NHALF, n))

    static int init_done = 0;
    static cudaStream_t s2 = nullptr;
    static cudaEvent_t evFork = nullptr, evJoin = nullptr, evA = nullptr, evC = nullptr;
    if (!init_done) {
        cudaFuncSetAttribute(gemm1_mma_kernel, cudaFuncAttributeMaxDynamicSharedMemorySize, G1_SMEM);
        cudaFuncSetAttribute(gemm2_mma_kernel, cudaFuncAttributeMaxDynamicSharedMemorySize, G2_SMEM);
        if (cudaStreamCreateWithFlags(&s2, cudaStreamNonBlocking) != cudaSuccess) s2 = nullptr;
        cudaEventCreateWithFlags(&evFork, cudaEventDisableTiming);
        cudaEventCreateWithFlags(&evJoin, cudaEventDisableTiming);
        cudaEventCreateWithFlags(&evA, cudaEventDisableTiming);
        cudaEventCreateWithFlags(&evC, cudaEventDisableTiming);
        init_done = 1;
    }

    setup_kernel<<<(n + 255) / 256, 256>>>(W1, W2, (const unsigned int*)ei, E * 2, n);

    if (s2) {
        cudaEventRecord(evFork, 0);
        cudaStreamWaitEvent(s2, evFork, 0);
        deg_count_kernel<<<2048, 256, 0, s2>>>(ei, E);
        scan1_kernel<<<NSCAN, 256, 0, s2>>>(n);
        scan3_kernel<<<(n + 256) / 256, 256, 0, s2>>>(n, (int)E, NSCAN);
        fill_kernel<<<2048, 256, 0, s2>>>(ei, E);
        cudaEventRecord(evJoin, s2);

        gemm1_mma_kernel<<<nblk, 256, G1_SMEM>>>(x, n);
        cudaStreamWaitEvent(0, evJoin, 0);

        // pipelined tail: g1a -> {g1b (s0) || m2a (s2)} -> m2b -> gather2
        gather1_kernel<<<(NHALF * 32 + 255) / 256, 256>>>(0, NHALF);
        cudaEventRecord(evA, 0);
        cudaStreamWaitEvent(s2, evA, 0);
        gemm2_mma_kernel<<<nblkA, 256, G2_SMEM, s2>>>(b1, 0, NHALF);
        cudaEventRecord(evC, s2);

        gather1_kernel<<<((n - NHALF) * 32 + 255) / 256, 256>>>(NHALF, n);
        gemm2_mma_kernel<<<nblkB, 256, G2_SMEM>>>(b1, NHALF, n);
        cudaStreamWaitEvent(0, evC, 0);
    } else {
        deg_count_kernel<<<2048, 256>>>(ei, E);
        scan1_kernel<<<NSCAN, 256>>>(n);
        scan3_kernel<<<(n + 256) / 256, 256>>>(n, (int)E, NSCAN);
        fill_kernel<<<2048, 256>>>(ei, E);
        gemm1_mma_kernel<<<nblk, 256, G1_SMEM>>>(x, n);
        gather1_kernel<<<(n * 32 + 255) / 256, 256>>>(0, n);
        gemm2_mma_kernel<<<nblk, 256, G2_SMEM>>>(b1, 0, n);
    }

    gather2_kernel<<<(n * 32 + 255) / 256, 256>>>(out, b2, n);
}

// round 17
// speedup vs baseline: 1.0221x; 1.0221x over previous
#include <cuda_runtime.h>
#include <cuda_bf16.h>
#include <cuda_fp16.h>
#include <mma.h>
#include <stdint.h>

using namespace nvcuda;

// ---------------------------------------------------------------------------
// 2-layer GCN on GB300 — CSR-gather + tensor-core GEMMs + dual-stream overlap.
// s0: setup -> gemm1 -(join)-> gather1 -> gemm2 -> gather2
// s2:      \-> deg_count -> scan1 -> scan3 -> fill -/
// Gathers use 8-wide neighbor unroll (MLP=8; they are latency-bound).
// ---------------------------------------------------------------------------

#define MAXN 100000
#define MAXE 2000000
#define DIN 128
#define DH  128
#define DOUT 64
#define SCAN_BLK 1024
#define NSCAN ((MAXN + SCAN_BLK - 1) / SCAN_BLK)   // 98

__device__ float  g_dinv[MAXN];
__device__ int    g_deg[MAXN];
__device__ int    g_fill[MAXN];
__device__ int    g_row_ptr[MAXN + 1];
__device__ int    g_partials[128];
__device__ int    g_col[MAXE];
__device__ __half g_h1[(size_t)MAXN * DH];
__device__ __half g_acc1[(size_t)MAXN * DH];
__device__ __half g_h2[(size_t)MAXN * DOUT];
__device__ __half g_w1h[DIN * DH];
__device__ __half g_w2h[DH * DOUT], g_w2l[DH * DOUT];
__device__ int    g_idx_is64;

__device__ __forceinline__ long long load_idx(const void* ei, long long pos, int is64) {
    if (is64) return ((const long long*)ei)[pos];
    return (long long)((const int*)ei)[pos];
}

// ---------------------------------------------------------------------------
__global__ void setup_kernel(const float* __restrict__ W1, const float* __restrict__ W2,
                             const unsigned int* __restrict__ w, long long nwords, int n) {
    int i = blockIdx.x * blockDim.x + threadIdx.x;
    if (i < DIN * DH) g_w1h[i] = __float2half_rn(W1[i]);
    if (i < DH * DOUT) {
        float wv = W2[i];
        __half h = __float2half_rn(wv);
        g_w2h[i] = h;
        g_w2l[i] = __float2half_rn(wv - __half2float(h));
    }
    if (i < n) { g_deg[i] = 0; g_fill[i] = 0; }
    if (blockIdx.x == 0) {
        __shared__ int any;
        if (threadIdx.x == 0) any = 0;
        __syncthreads();
        long long limit = nwords < 8192 ? nwords : 8192;
        for (long long j = 1 + 2 * (long long)threadIdx.x; j < limit; j += 512)
            if (w[j] != 0u) any = 1;
        __syncthreads();
        if (threadIdx.x == 0) g_idx_is64 = any ? 0 : 1;
    }
}

__global__ void deg_count_kernel(const void* __restrict__ ei, long long E) {
    const int is64 = g_idx_is64;
    long long i = (long long)blockIdx.x * blockDim.x + threadIdx.x;
    long long stride = (long long)gridDim.x * blockDim.x;
    for (; i < E; i += stride) {
        long long d = load_idx(ei, E + i, is64);
        if (d >= 0 && d < MAXN) atomicAdd(&g_deg[(int)d], 1);
    }
}

// --- 2-level exclusive scan of g_deg -> g_row_ptr, fused dinv ---------------
__global__ __launch_bounds__(256) void scan1_kernel(int n) {
    __shared__ int wsum[8], woff[8];
    const int t = threadIdx.x, lane = t & 31, wid = t >> 5;
    const int base = blockIdx.x * SCAN_BLK;
    const int i0 = base + t * 4;
    int v[4];
#pragma unroll
    for (int k = 0; k < 4; k++) v[k] = (i0 + k < n) ? g_deg[i0 + k] : 0;
#pragma unroll
    for (int k = 0; k < 4; k++)
        if (i0 + k < n) g_dinv[i0 + k] = rsqrtf((float)(v[k] + 1));
    int tsum = v[0] + v[1] + v[2] + v[3];
    int s = tsum;
#pragma unroll
    for (int off = 1; off < 32; off <<= 1) {
        int u = __shfl_up_sync(0xFFFFFFFFu, s, off);
        if (lane >= off) s += u;
    }
    if (lane == 31) wsum[wid] = s;
    __syncthreads();
    if (t == 0) {
        int run = 0;
#pragma unroll
        for (int w = 0; w < 8; w++) { woff[w] = run; run += wsum[w]; }
        g_partials[blockIdx.x] = run;
    }
    __syncthreads();
    int excl = woff[wid] + (s - tsum);
    int run = excl;
#pragma unroll
    for (int k = 0; k < 4; k++) {
        if (i0 + k < n) g_row_ptr[i0 + k] = run;
        run += v[k];
    }
}

__global__ __launch_bounds__(256) void scan3_kernel(int n, int E, int nblk) {
    __shared__ int soff[128];
    const int t = threadIdx.x;
    if (t < 32) {
        int v[4];
#pragma unroll
        for (int k = 0; k < 4; k++) {
            int idx = t * 4 + k;
            v[k] = (idx < nblk) ? g_partials[idx] : 0;
        }
        int tsum = v[0] + v[1] + v[2] + v[3];
        int s = tsum;
#pragma unroll
        for (int off = 1; off < 32; off <<= 1) {
            int u = __shfl_up_sync(0xFFFFFFFFu, s, off);
            if (t >= off) s += u;
        }
        int run = s - tsum;
#pragma unroll
        for (int k = 0; k < 4; k++) {
            soff[t * 4 + k] = run;
            run += v[k];
        }
    }
    __syncthreads();
    int i = blockIdx.x * blockDim.x + t;
    if (i < n) g_row_ptr[i] += soff[i / SCAN_BLK];
    if (i == n) g_row_ptr[n] = E;
}

__global__ void fill_kernel(const void* __restrict__ ei, long long E) {
    const int is64 = g_idx_is64;
    long long i = (long long)blockIdx.x * blockDim.x + threadIdx.x;
    long long stride = (long long)gridDim.x * blockDim.x;
    for (; i < E; i += stride) {
        long long s = load_idx(ei, i, is64);
        long long d = load_idx(ei, E + i, is64);
        if (s < 0 || s >= MAXN || d < 0 || d >= MAXN) continue;
        int pos = g_row_ptr[(int)d] + atomicAdd(&g_fill[(int)d], 1);
        g_col[pos] = (int)s;
    }
}

// ---------------------------------------------------------------------------
// GEMM1: h1 = fp16( fp16(x) @ fp16(W1) ), unscaled.
// ---------------------------------------------------------------------------
#define G1_LDX 40
#define G1_LDW 136
#define G1_SMEM 55296

__global__ __launch_bounds__(256, 2) void gemm1_mma_kernel(
    const float* __restrict__ x, int n)
{
    extern __shared__ char smem[];
    __half* sX[2] = { (__half*)smem, (__half*)(smem + 10240) };
    __half* sWh = (__half*)(smem + 20480);

    const int tid = threadIdx.x;
    const int wid = tid >> 5, lane = tid & 31;
    const int wm = wid >> 1, wn = wid & 1;
    const int row0 = blockIdx.x * 128;
    const int srow = tid >> 1, hc = tid & 1;
    const int grow_st = row0 + srow;
    const bool rowok = grow_st < n;

    for (int i = tid; i < 2048; i += 256) {
        int r = i >> 4, c = i & 15;
        *(uint4*)&sWh[r * G1_LDW + c * 8] = ((const uint4*)(g_w1h + (size_t)r * DH))[c];
    }

    wmma::fragment<wmma::accumulator, 16, 16, 16, float> acc[2][4];
#pragma unroll
    for (int mi = 0; mi < 2; mi++)
#pragma unroll
        for (int ni = 0; ni < 4; ni++) wmma::fill_fragment(acc[mi][ni], 0.f);

    float4 tmp[4];
    if (rowok) {
#pragma unroll
        for (int j = 0; j < 4; j++)
            tmp[j] = *(const float4*)&x[(size_t)grow_st * DIN + hc * 16 + j * 4];
    } else {
#pragma unroll
        for (int j = 0; j < 4; j++) tmp[j] = make_float4(0.f, 0.f, 0.f, 0.f);
    }

    for (int k0 = 0; k0 < 4; k0++) {
        const int b = k0 & 1;
        {
            __half hh[16];
            const float* tf = (const float*)tmp;
#pragma unroll
            for (int j = 0; j < 16; j++) hh[j] = __float2half_rn(tf[j]);
            *(uint4*)&sX[b][srow * G1_LDX + hc * 16]     = *(uint4*)&hh[0];
            *(uint4*)&sX[b][srow * G1_LDX + hc * 16 + 8] = *(uint4*)&hh[8];
        }
        if (k0 < 3 && rowok) {
#pragma unroll
            for (int j = 0; j < 4; j++)
                tmp[j] = *(const float4*)&x[(size_t)grow_st * DIN + (k0 + 1) * 32 + hc * 16 + j * 4];
        }
        __syncthreads();
#pragma unroll
        for (int kk = 0; kk < 32; kk += 16) {
            const int kr = k0 * 32 + kk;
            wmma::fragment<wmma::matrix_a, 16, 16, 16, __half, wmma::row_major> ah[2];
#pragma unroll
            for (int mi = 0; mi < 2; mi++)
                wmma::load_matrix_sync(ah[mi], sX[b] + (wm * 32 + mi * 16) * G1_LDX + kk, G1_LDX);
#pragma unroll
            for (int ni = 0; ni < 4; ni++) {
                wmma::fragment<wmma::matrix_b, 16, 16, 16, __half, wmma::row_major> bh;
                wmma::load_matrix_sync(bh, sWh + kr * G1_LDW + wn * 64 + ni * 16, G1_LDW);
#pragma unroll
                for (int mi = 0; mi < 2; mi++)
                    wmma::mma_sync(acc[mi][ni], ah[mi], bh, acc[mi][ni]);
            }
        }
    }

    __syncthreads();
    float* scratch = (float*)smem + wid * (32 * 36);
#pragma unroll
    for (int h = 0; h < 2; h++) {
        if (h) __syncwarp();
        wmma::store_matrix_sync(scratch,            acc[0][2*h],   36, wmma::mem_row_major);
        wmma::store_matrix_sync(scratch + 16,       acc[0][2*h+1], 36, wmma::mem_row_major);
        wmma::store_matrix_sync(scratch + 16*36,    acc[1][2*h],   36, wmma::mem_row_major);
        wmma::store_matrix_sync(scratch + 16*36+16, acc[1][2*h+1], 36, wmma::mem_row_major);
        __syncwarp();
        int grow = row0 + wm * 32 + lane;
        if (grow < n) {
            const float* sr = scratch + lane * 36;
            __half2 hh[16];
#pragma unroll
            for (int j = 0; j < 16; j++)
                hh[j] = __floats2half2_rn(sr[2*j], sr[2*j+1]);
            uint4* dst = (uint4*)&g_h1[(size_t)grow * DH + wn * 64 + h * 32];
#pragma unroll
            for (int q = 0; q < 4; q++) dst[q] = ((uint4*)hh)[q];
        }
    }
}

// ---------------------------------------------------------------------------
// gather1: acc1[v] = fp16(dinv[v]*h1[v] + sum dinv[s]*h1[s]).  MLP=8.
// ---------------------------------------------------------------------------
__global__ __launch_bounds__(256) void gather1_kernel(int n)
{
    const int lane = threadIdx.x & 31;
    const int v = (int)((blockIdx.x * blockDim.x + threadIdx.x) >> 5);
    if (v >= n) return;

    const int start = g_row_ptr[v], end = g_row_ptr[v + 1];
    const float dvv = g_dinv[v];
    float4 acc;
    {
        uint2 u = *(const uint2*)&g_h1[(size_t)v * DH + lane * 4];
        float2 f0 = __half22float2(*(__half2*)&u.x);
        float2 f1 = __half22float2(*(__half2*)&u.y);
        acc = make_float4(dvv * f0.x, dvv * f0.y, dvv * f1.x, dvv * f1.y);
    }

    for (int b = start; b < end; b += 32) {
        const int cnt = min(32, end - b);
        int idx = (lane < cnt) ? g_col[b + lane] : 0;
        float dvl = (lane < cnt) ? g_dinv[idx] : 0.f;
        int j = 0;
        for (; j + 8 <= cnt; j += 8) {
            int ss[8]; float dd[8]; uint2 uu[8];
#pragma unroll
            for (int q = 0; q < 8; q++) {
                ss[q] = __shfl_sync(0xFFFFFFFFu, idx, j + q);
                dd[q] = __shfl_sync(0xFFFFFFFFu, dvl, j + q);
            }
#pragma unroll
            for (int q = 0; q < 8; q++)
                uu[q] = *(const uint2*)&g_h1[(size_t)ss[q] * DH + lane * 4];
#pragma unroll
            for (int q = 0; q < 8; q++) {
                float2 f0 = __half22float2(*(__half2*)&uu[q].x);
                float2 f1 = __half22float2(*(__half2*)&uu[q].y);
                acc.x = fmaf(dd[q], f0.x, acc.x); acc.y = fmaf(dd[q], f0.y, acc.y);
                acc.z = fmaf(dd[q], f1.x, acc.z); acc.w = fmaf(dd[q], f1.y, acc.w);
            }
        }
        for (; j + 4 <= cnt; j += 4) {
            int ss[4]; float dd[4]; uint2 uu[4];
#pragma unroll
            for (int q = 0; q < 4; q++) {
                ss[q] = __shfl_sync(0xFFFFFFFFu, idx, j + q);
                dd[q] = __shfl_sync(0xFFFFFFFFu, dvl, j + q);
            }
#pragma unroll
            for (int q = 0; q < 4; q++)
                uu[q] = *(const uint2*)&g_h1[(size_t)ss[q] * DH + lane * 4];
#pragma unroll
            for (int q = 0; q < 4; q++) {
                float2 f0 = __half22float2(*(__half2*)&uu[q].x);
                float2 f1 = __half22float2(*(__half2*)&uu[q].y);
                acc.x = fmaf(dd[q], f0.x, acc.x); acc.y = fmaf(dd[q], f0.y, acc.y);
                acc.z = fmaf(dd[q], f1.x, acc.z); acc.w = fmaf(dd[q], f1.y, acc.w);
            }
        }
        for (; j < cnt; j++) {
            int s = __shfl_sync(0xFFFFFFFFu, idx, j);
            float d = __shfl_sync(0xFFFFFFFFu, dvl, j);
            uint2 u = *(const uint2*)&g_h1[(size_t)s * DH + lane * 4];
            float2 f0 = __half22float2(*(__half2*)&u.x);
            float2 f1 = __half22float2(*(__half2*)&u.y);
            acc.x = fmaf(d, f0.x, acc.x); acc.y = fmaf(d, f0.y, acc.y);
            acc.z = fmaf(d, f1.x, acc.z); acc.w = fmaf(d, f1.y, acc.w);
        }
    }
    uint2 o;
    *(__half2*)&o.x = __floats2half2_rn(acc.x, acc.y);
    *(__half2*)&o.y = __floats2half2_rn(acc.z, acc.w);
    *(uint2*)&g_acc1[(size_t)v * DH + lane * 4] = o;
}

// ---------------------------------------------------------------------------
// GEMM2: h2 = fp16((relu(dinv*acc1+b1) @ (W2h+W2l)) * dinv[row]).
// ---------------------------------------------------------------------------
#define G2_LDX 40
#define G2_LDW 72
#define G2_SMEM 57856

__global__ __launch_bounds__(256, 2) void gemm2_mma_kernel(
    const float* __restrict__ b1, int n)
{
    extern __shared__ char smem[];
    __half* sX[2] = { (__half*)smem, (__half*)(smem + 10240) };
    __half* sWh = (__half*)(smem + 20480);
    __half* sWl = (__half*)(smem + 38912);
    float*  sb1 = (float*)(smem + 57344);

    const int tid = threadIdx.x;
    const int wid = tid >> 5, lane = tid & 31;
    const int wm = wid >> 1, wn = wid & 1;
    const int row0 = blockIdx.x * 128;
    const int srow = tid >> 1, hc = tid & 1;
    const int grow_st = row0 + srow;
    const bool rowok = grow_st < n;
    const float dv_st = rowok ? g_dinv[grow_st] : 0.f;

    if (tid < 32) ((float4*)sb1)[tid] = ((const float4*)b1)[tid];
    for (int i = tid; i < 1024; i += 256) {
        int r = i >> 3, c = i & 7;
        *(uint4*)&sWh[r * G2_LDW + c * 8] = ((const uint4*)(g_w2h + (size_t)r * DOUT))[c];
        *(uint4*)&sWl[r * G2_LDW + c * 8] = ((const uint4*)(g_w2l + (size_t)r * DOUT))[c];
    }

    wmma::fragment<wmma::accumulator, 16, 16, 16, float> acc[2][2];
#pragma unroll
    for (int mi = 0; mi < 2; mi++)
#pragma unroll
        for (int ni = 0; ni < 2; ni++) wmma::fill_fragment(acc[mi][ni], 0.f);

    uint4 tmp16[2];
    if (rowok) {
#pragma unroll
        for (int j = 0; j < 2; j++)
            tmp16[j] = *(const uint4*)&g_acc1[(size_t)grow_st * DH + hc * 16 + j * 8];
    } else {
        tmp16[0] = tmp16[1] = make_uint4(0u, 0u, 0u, 0u);
    }

    __syncthreads();

    for (int k0 = 0; k0 < 4; k0++) {
        const int b = k0 & 1;
        {
            __half hh[16];
            const __half2* th = (const __half2*)tmp16;
#pragma unroll
            for (int j = 0; j < 8; j++) {
                float2 f = __half22float2(th[j]);
                hh[2*j]   = __float2half_rn(fmaxf(fmaf(dv_st, f.x, sb1[k0 * 32 + hc * 16 + 2*j]),   0.f));
                hh[2*j+1] = __float2half_rn(fmaxf(fmaf(dv_st, f.y, sb1[k0 * 32 + hc * 16 + 2*j+1]), 0.f));
            }
            *(uint4*)&sX[b][srow * G2_LDX + hc * 16]     = *(uint4*)&hh[0];
            *(uint4*)&sX[b][srow * G2_LDX + hc * 16 + 8] = *(uint4*)&hh[8];
        }
        if (k0 < 3 && rowok) {
#pragma unroll
            for (int j = 0; j < 2; j++)
                tmp16[j] = *(const uint4*)&g_acc1[(size_t)grow_st * DH + (k0 + 1) * 32 + hc * 16 + j * 8];
        }
        __syncthreads();
#pragma unroll
        for (int kk = 0; kk < 32; kk += 16) {
            const int kr = k0 * 32 + kk;
            wmma::fragment<wmma::matrix_a, 16, 16, 16, __half, wmma::row_major> ah[2];
#pragma unroll
            for (int mi = 0; mi < 2; mi++)
                wmma::load_matrix_sync(ah[mi], sX[b] + (wm * 32 + mi * 16) * G2_LDX + kk, G2_LDX);
#pragma unroll
            for (int ni = 0; ni < 2; ni++) {
                wmma::fragment<wmma::matrix_b, 16, 16, 16, __half, wmma::row_major> bh, bl;
                wmma::load_matrix_sync(bh, sWh + kr * G2_LDW + wn * 32 + ni * 16, G2_LDW);
                wmma::load_matrix_sync(bl, sWl + kr * G2_LDW + wn * 32 + ni * 16, G2_LDW);
#pragma unroll
                for (int mi = 0; mi < 2; mi++) {
                    wmma::mma_sync(acc[mi][ni], ah[mi], bh, acc[mi][ni]);
                    wmma::mma_sync(acc[mi][ni], ah[mi], bl, acc[mi][ni]);
                }
            }
        }
    }

    __syncthreads();
    float* scratch = (float*)(smem + 20480) + wid * (32 * 36);
    wmma::store_matrix_sync(scratch,            acc[0][0], 36, wmma::mem_row_major);
    wmma::store_matrix_sync(scratch + 16,       acc[0][1], 36, wmma::mem_row_major);
    wmma::store_matrix_sync(scratch + 16*36,    acc[1][0], 36, wmma::mem_row_major);
    wmma::store_matrix_sync(scratch + 16*36+16, acc[1][1], 36, wmma::mem_row_major);
    __syncwarp();
    int grow = row0 + wm * 32 + lane;
    if (grow < n) {
        float dv = g_dinv[grow];
        const float* sr = scratch + lane * 36;
        __half2 hh[16];
#pragma unroll
        for (int j = 0; j < 16; j++)
            hh[j] = __floats2half2_rn(sr[2*j] * dv, sr[2*j+1] * dv);
        uint4* dst = (uint4*)&g_h2[(size_t)grow * DOUT + wn * 32];
#pragma unroll
        for (int q = 0; q < 4; q++) dst[q] = ((uint4*)hh)[q];
    }
}

// ---------------------------------------------------------------------------
// gather2: out[v] = dinv[v]*(h2[v] + sum h2[s]) + b2.  MLP=8.
// ---------------------------------------------------------------------------
__global__ __launch_bounds__(256) void gather2_kernel(
    float* __restrict__ out, const float* __restrict__ b2, int n)
{
    const int lane = threadIdx.x & 31;
    const int v = (int)((blockIdx.x * blockDim.x + threadIdx.x) >> 5);
    if (v >= n) return;

    const int start = g_row_ptr[v], end = g_row_ptr[v + 1];
    float2 acc = __half22float2(*(const __half2*)&g_h2[(size_t)v * DOUT + lane * 2]);

    for (int b = start; b < end; b += 32) {
        const int cnt = min(32, end - b);
        int idx = (lane < cnt) ? g_col[b + lane] : 0;
        int j = 0;
        for (; j + 8 <= cnt; j += 8) {
            int ss[8]; uint32_t uu[8];
#pragma unroll
            for (int q = 0; q < 8; q++)
                ss[q] = __shfl_sync(0xFFFFFFFFu, idx, j + q);
#pragma unroll
            for (int q = 0; q < 8; q++)
                uu[q] = *(const uint32_t*)&g_h2[(size_t)ss[q] * DOUT + lane * 2];
#pragma unroll
            for (int q = 0; q < 8; q++) {
                float2 a = __half22float2(*(__half2*)&uu[q]);
                acc.x += a.x; acc.y += a.y;
            }
        }
        for (; j + 4 <= cnt; j += 4) {
            int ss[4]; uint32_t uu[4];
#pragma unroll
            for (int q = 0; q < 4; q++)
                ss[q] = __shfl_sync(0xFFFFFFFFu, idx, j + q);
#pragma unroll
            for (int q = 0; q < 4; q++)
                uu[q] = *(const uint32_t*)&g_h2[(size_t)ss[q] * DOUT + lane * 2];
#pragma unroll
            for (int q = 0; q < 4; q++) {
                float2 a = __half22float2(*(__half2*)&uu[q]);
                acc.x += a.x; acc.y += a.y;
            }
        }
        for (; j < cnt; j++) {
            int s = __shfl_sync(0xFFFFFFFFu, idx, j);
            float2 a = __half22float2(*(const __half2*)&g_h2[(size_t)s * DOUT + lane * 2]);
            acc.x += a.x; acc.y += a.y;
        }
    }
    float dv = g_dinv[v];
    float2 bb = *(const float2*)&b2[lane * 2];
    *(float2*)&out[(size_t)v * DOUT + lane * 2] =
        make_float2(fmaf(acc.x, dv, bb.x), fmaf(acc.y, dv, bb.y));
}

// ---------------------------------------------------------------------------
extern "C" void kernel_launch(void* const* d_in, const int* in_sizes, int n_in,
                              void* d_out, int out_size)
{
    const float* x = nullptr; const float* W1 = nullptr; const float* b1 = nullptr;
    const float* W2 = nullptr; const float* b2 = nullptr; const void* ei = nullptr;
    long long ei_elems = 0;
    for (int i = 0; i < n_in; i++) {
        switch (in_sizes[i]) {
            case MAXN * DIN: x  = (const float*)d_in[i]; break;
            case DIN * DH:   W1 = (const float*)d_in[i]; break;
            case DH:         b1 = (const float*)d_in[i]; break;
            case DH * DOUT:  W2 = (const float*)d_in[i]; break;
            case DOUT:       b2 = (const float*)d_in[i]; break;
            default:         ei = d_in[i]; ei_elems = in_sizes[i]; break;
        }
    }
    float* out = (float*)d_out;
    const int n = MAXN;
    const long long E = ei_elems / 2;
    const int nblk = (n + 127) / 128;

    static int init_done = 0;
    static cudaStream_t s2 = nullptr;
    static cudaEvent_t evFork = nullptr, evJoin = nullptr;
    if (!init_done) {
        cudaFuncSetAttribute(gemm1_mma_kernel, cudaFuncAttributeMaxDynamicSharedMemorySize, G1_SMEM);
        cudaFuncSetAttribute(gemm2_mma_kernel, cudaFuncAttributeMaxDynamicSharedMemorySize, G2_SMEM);
        if (cudaStreamCreateWithFlags(&s2, cudaStreamNonBlocking) != cudaSuccess) s2 = nullptr;
        cudaEventCreateWithFlags(&evFork, cudaEventDisableTiming);
        cudaEventCreateWithFlags(&evJoin, cudaEventDisableTiming);
        init_done = 1;
    }

    setup_kernel<<<(n + 255) / 256, 256>>>(W1, W2, (const unsigned int*)ei, E * 2, n);

    if (s2) {
        cudaEventRecord(evFork, 0);
        cudaStreamWaitEvent(s2, evFork, 0);
        deg_count_kernel<<<2048, 256, 0, s2>>>(ei, E);
        scan1_kernel<<<NSCAN, 256, 0, s2>>>(n);
        scan3_kernel<<<(n + 256) / 256, 256, 0, s2>>>(n, (int)E, NSCAN);
        fill_kernel<<<2048, 256, 0, s2>>>(ei, E);
        cudaEventRecord(evJoin, s2);

        gemm1_mma_kernel<<<nblk, 256, G1_SMEM>>>(x, n);
        cudaStreamWaitEvent(0, evJoin, 0);
    } else {
        deg_count_kernel<<<2048, 256>>>(ei, E);
        scan1_kernel<<<NSCAN, 256>>>(n);
        scan3_kernel<<<(n + 256) / 256, 256>>>(n, (int)E, NSCAN);
        fill_kernel<<<2048, 256>>>(ei, E);
        gemm1_mma_kernel<<<nblk, 256, G1_SMEM>>>(x, n);
    }

    gather1_kernel<<<(n * 32 + 255) / 256, 256>>>(n);
    gemm2_mma_kernel<<<nblk, 256, G2_SMEM>>>(b1, n);
    gather2_kernel<<<(n * 32 + 255) / 256, 256>>>(out, b2, n);
}